// round 3
// baseline (speedup 1.0000x reference)
#include <cuda_runtime.h>
#include <cuda_bf16.h>

#define L_SEQ 1024
#define NPOS  64
#define ROWS_TOTAL (4 * 12 * 1024)

// Scratch for the interpolated position logits: lint[row][n] = q[row,:] . pe[:,n]
__device__ float g_lint[(size_t)ROWS_TOTAL * NPOS];

// ---------------------------------------------------------------------------
// Kernel 1: lint = query @ pos_emb   ([49152,64] @ [64,64])
// 32 rows per block. Thread t: n = t>>2 (output col), db = t&3 (16-wide d chunk).
// pe column slice lives in registers for all 32 rows; cross-chunk reduction via
// shfl_xor over 4 adjacent lanes. No syncs in the row loop.
// ---------------------------------------------------------------------------
__global__ __launch_bounds__(256) void gemv_kernel(
    const float* __restrict__ q, const float* __restrict__ pe)
{
    const int t  = threadIdx.x;
    const int n  = t >> 2;   // 0..63
    const int db = t & 3;    // 0..3

    float per[16];
    #pragma unroll
    for (int dd = 0; dd < 16; dd++)
        per[dd] = __ldg(&pe[(db * 16 + dd) * NPOS + n]);

    __shared__ float qsh[32 * 64];
    const int base = blockIdx.x * 32;
    {
        const float4* src = reinterpret_cast<const float4*>(q + (size_t)base * 64);
        float4* dst = reinterpret_cast<float4*>(qsh);
        dst[t]       = src[t];
        dst[t + 256] = src[t + 256];
    }
    __syncthreads();

    #pragma unroll 4
    for (int r = 0; r < 32; r++) {
        const float4* qr = reinterpret_cast<const float4*>(qsh + r * 64 + db * 16);
        float acc = 0.0f;
        #pragma unroll
        for (int k = 0; k < 4; k++) {
            const float4 qq = qr[k];
            acc = fmaf(qq.x, per[4*k+0], acc);
            acc = fmaf(qq.y, per[4*k+1], acc);
            acc = fmaf(qq.z, per[4*k+2], acc);
            acc = fmaf(qq.w, per[4*k+3], acc);
        }
        acc += __shfl_xor_sync(0xffffffffu, acc, 1);
        acc += __shfl_xor_sync(0xffffffffu, acc, 2);
        if (db == 0) g_lint[(size_t)(base + r) * NPOS + n] = acc;
    }
}

// ---------------------------------------------------------------------------
// Kernel 2: per row: sigmoid gates (diag zeroed), clamped suffix-sum position,
// interpolate from lint row. Fast path: pos >= 63 (clamped) -> out = Lg[63].
// ---------------------------------------------------------------------------
__global__ __launch_bounds__(256) void cope_main(
    const float* __restrict__ attn,
    float* __restrict__ out)
{
    const int row  = blockIdx.x;
    const int diag = row & (L_SEQ - 1);
    const int t    = threadIdx.x;
    const int lane = t & 31;
    const int wid  = t >> 5;

    __shared__ float Lg[NPOS + 1];   // Lg[64] duplicates Lg[63] (w==0 there)
    __shared__ float warpsum[8];

    // Kick off both global loads immediately.
    const float4 v = __ldcs(reinterpret_cast<const float4*>(attn) + (size_t)row * (L_SEQ / 4) + t);
    if (t < NPOS + 1) {
        const int idx = (t < NPOS) ? t : (NPOS - 1);
        Lg[t] = g_lint[(size_t)row * NPOS + idx];
    }

    // Sigmoid + diagonal zero.
    float g0 = 1.0f / (1.0f + __expf(-v.x));
    float g1 = 1.0f / (1.0f + __expf(-v.y));
    float g2 = 1.0f / (1.0f + __expf(-v.z));
    float g3 = 1.0f / (1.0f + __expf(-v.w));
    const int c0 = t << 2;
    if (c0     == diag) g0 = 0.0f;
    if (c0 + 1 == diag) g1 = 0.0f;
    if (c0 + 2 == diag) g2 = 0.0f;
    if (c0 + 3 == diag) g3 = 0.0f;
    const float s = g0 + g1 + g2 + g3;

    // Warp inclusive scan of per-thread sums.
    float incl = s;
    #pragma unroll
    for (int off = 1; off < 32; off <<= 1) {
        const float nv = __shfl_up_sync(0xffffffffu, incl, off);
        if (lane >= off) incl += nv;
    }
    if (lane == 31) warpsum[wid] = incl;
    __syncthreads();   // warpsum + Lg visible

    float wpre = 0.0f, total = 0.0f;
    #pragma unroll
    for (int k = 0; k < 8; k++) {
        const float wsk = warpsum[k];
        total += wsk;
        if (k < wid) wpre += wsk;
    }
    const float excl = wpre + incl - s;   // exclusive prefix at element c0

    // Suffix (inclusive) sums = total - exclusive prefix.
    const float p0 = total - excl;
    const float p1 = p0 - g0;
    const float p2 = p1 - g1;
    const float p3 = p2 - g2;

    const float Lg63 = Lg[NPOS - 1];
    float4 o;
    if (p3 >= 63.0f) {
        // All four positions clamp to 63; w == 0.
        o.x = Lg63; o.y = Lg63; o.z = Lg63; o.w = Lg63;
    } else {
        float p, pf, w; int fi;
        p = fminf(fmaxf(p0, 0.0f), 63.0f); pf = floorf(p); w = p - pf; fi = (int)pf;
        o.x = Lg[fi] + w * (Lg[fi + 1] - Lg[fi]);
        p = fminf(fmaxf(p1, 0.0f), 63.0f); pf = floorf(p); w = p - pf; fi = (int)pf;
        o.y = Lg[fi] + w * (Lg[fi + 1] - Lg[fi]);
        p = fminf(fmaxf(p2, 0.0f), 63.0f); pf = floorf(p); w = p - pf; fi = (int)pf;
        o.z = Lg[fi] + w * (Lg[fi + 1] - Lg[fi]);
        p = fminf(fmaxf(p3, 0.0f), 63.0f); pf = floorf(p); w = p - pf; fi = (int)pf;
        o.w = Lg[fi] + w * (Lg[fi + 1] - Lg[fi]);
    }

    __stcs(reinterpret_cast<float4*>(out) + (size_t)row * (L_SEQ / 4) + t, o);
}

extern "C" void kernel_launch(void* const* d_in, const int* in_sizes, int n_in,
                              void* d_out, int out_size) {
    const float* query = (const float*)d_in[0];   // [4,12,1024,64]
    const float* attn  = (const float*)d_in[1];   // [4,12,1024,1024]
    const float* pe    = (const float*)d_in[2];   // [64,64]
    float* out = (float*)d_out;                   // [4,12,1024,1024]

    const int rows = in_sizes[1] / L_SEQ;         // 49152
    gemv_kernel<<<rows / 32, 256>>>(query, pe);
    cope_main<<<rows, 256>>>(attn, out);
}

// round 4
// speedup vs baseline: 1.3071x; 1.3071x over previous
#include <cuda_runtime.h>
#include <cuda_bf16.h>

#define L_SEQ 1024
#define NPOS  64
#define ROWS_TOTAL (4 * 12 * 1024)

// Scratch: lint[row][n] = q[row,:] . pe[:,n]
__device__ float g_lint[(size_t)ROWS_TOTAL * NPOS];

// ---------------------------------------------------------------------------
// Kernel 1: lint = query @ pos_emb   ([49152,64] @ [64,64])
// Block = 256 threads = 8 warps, handles 32 rows.
//   lane  -> row (32 rows per block)
//   warp  -> output cols [8w, 8w+8)
// q row held in registers (16 float4); pe staged in shared, inner-loop reads
// are warp-broadcast LDS.128 (1-cycle wavefronts). 512 FMA : 128 LDS per
// thread -> FMA-bound.
// ---------------------------------------------------------------------------
__global__ __launch_bounds__(256) void gemv_kernel(
    const float* __restrict__ q, const float* __restrict__ pe)
{
    __shared__ float pesh[64 * 64];   // [d][n], row-major, 16KB
    const int t    = threadIdx.x;
    const int lane = t & 31;
    const int w    = t >> 5;

    // Stage pe (4096 floats, coalesced).
    {
        const float4* src = reinterpret_cast<const float4*>(pe);
        float4*       dst = reinterpret_cast<float4*>(pesh);
        #pragma unroll
        for (int i = 0; i < 4; i++) dst[t + 256 * i] = __ldg(&src[t + 256 * i]);
    }

    // Load this lane's q row into registers (redundant across warps; L1-hit).
    const int row = blockIdx.x * 32 + lane;
    float4 qreg[16];
    {
        const float4* qr = reinterpret_cast<const float4*>(q + (size_t)row * 64);
        #pragma unroll
        for (int i = 0; i < 16; i++) qreg[i] = __ldg(&qr[i]);
    }
    __syncthreads();

    float acc[8] = {0, 0, 0, 0, 0, 0, 0, 0};
    const int cb = w * 8;
    #pragma unroll
    for (int kk = 0; kk < 16; kk++) {
        const float qk[4] = {qreg[kk].x, qreg[kk].y, qreg[kk].z, qreg[kk].w};
        #pragma unroll
        for (int j = 0; j < 4; j++) {
            const int k = kk * 4 + j;
            const float4 p0 = *reinterpret_cast<const float4*>(&pesh[k * NPOS + cb]);
            const float4 p1 = *reinterpret_cast<const float4*>(&pesh[k * NPOS + cb + 4]);
            acc[0] = fmaf(qk[j], p0.x, acc[0]);
            acc[1] = fmaf(qk[j], p0.y, acc[1]);
            acc[2] = fmaf(qk[j], p0.z, acc[2]);
            acc[3] = fmaf(qk[j], p0.w, acc[3]);
            acc[4] = fmaf(qk[j], p1.x, acc[4]);
            acc[5] = fmaf(qk[j], p1.y, acc[5]);
            acc[6] = fmaf(qk[j], p1.z, acc[6]);
            acc[7] = fmaf(qk[j], p1.w, acc[7]);
        }
    }

    float4* dst = reinterpret_cast<float4*>(&g_lint[(size_t)row * NPOS + cb]);
    dst[0] = make_float4(acc[0], acc[1], acc[2], acc[3]);
    dst[1] = make_float4(acc[4], acc[5], acc[6], acc[7]);
}

// ---------------------------------------------------------------------------
// Kernel 2: per row of 1024: gates = sigmoid(attn) (diag zeroed),
// pos = clamp(suffix_sum, 0, 63), out = lerp(Lg[floor], Lg[floor+1], frac).
// 128 threads; thread t owns elements [4t,4t+4) and [512+4t, 512+4t+4)
// (two perfectly-coalesced float4 segments per warp instruction).
// ---------------------------------------------------------------------------
__global__ __launch_bounds__(128) void cope_main(
    const float* __restrict__ attn,
    float* __restrict__ out)
{
    const int row  = blockIdx.x;
    const int diag = row & (L_SEQ - 1);
    const int t    = threadIdx.x;
    const int lane = t & 31;
    const int w    = t >> 5;

    __shared__ float Lg[NPOS + 1];        // Lg[64] = Lg[63] (w==0 there)
    __shared__ float wsumA[4], wsumB[4];

    const float4* arow = reinterpret_cast<const float4*>(attn) + (size_t)row * (L_SEQ / 4);
    const float4 va = __ldcs(&arow[t]);
    const float4 vb = __ldcs(&arow[t + 128]);
    if (t < NPOS + 1) {
        const int idx = (t < NPOS) ? t : (NPOS - 1);
        Lg[t] = g_lint[(size_t)row * NPOS + idx];
    }

    float g[8];
    g[0] = 1.0f / (1.0f + __expf(-va.x));
    g[1] = 1.0f / (1.0f + __expf(-va.y));
    g[2] = 1.0f / (1.0f + __expf(-va.z));
    g[3] = 1.0f / (1.0f + __expf(-va.w));
    g[4] = 1.0f / (1.0f + __expf(-vb.x));
    g[5] = 1.0f / (1.0f + __expf(-vb.y));
    g[6] = 1.0f / (1.0f + __expf(-vb.z));
    g[7] = 1.0f / (1.0f + __expf(-vb.w));

    const int cA = t << 2;            // first element of chunk A
    const int cB = 512 + (t << 2);    // first element of chunk B
    #pragma unroll
    for (int i = 0; i < 4; i++) if (cA + i == diag) g[i] = 0.0f;
    #pragma unroll
    for (int i = 0; i < 4; i++) if (cB + i == diag) g[4 + i] = 0.0f;

    const float sA = g[0] + g[1] + g[2] + g[3];
    const float sB = g[4] + g[5] + g[6] + g[7];

    // Warp inclusive scans over the two chunk sums.
    float iA = sA, iB = sB;
    #pragma unroll
    for (int off = 1; off < 32; off <<= 1) {
        const float nA = __shfl_up_sync(0xffffffffu, iA, off);
        const float nB = __shfl_up_sync(0xffffffffu, iB, off);
        if (lane >= off) { iA += nA; iB += nB; }
    }
    if (lane == 31) { wsumA[w] = iA; wsumB[w] = iB; }
    __syncthreads();   // wsum* + Lg visible

    float totA = 0.0f, totB = 0.0f, preA = 0.0f, preB = 0.0f;
    #pragma unroll
    for (int k = 0; k < 4; k++) {
        const float a = wsumA[k], b = wsumB[k];
        totA += a; totB += b;
        if (k < w) { preA += a; preB += b; }
    }
    const float total = totA + totB;
    const float exclA = preA + iA - sA;          // exclusive prefix at cA
    const float exclB = totA + preB + iB - sB;   // exclusive prefix at cB

    const float Lg63 = Lg[NPOS - 1];
    float4 oA, oB;

    // Chunk A suffix positions.
    {
        const float p0 = total - exclA;
        const float p1 = p0 - g[0];
        const float p2 = p1 - g[1];
        const float p3 = p2 - g[2];
        if (p3 >= 63.0f) {
            oA.x = Lg63; oA.y = Lg63; oA.z = Lg63; oA.w = Lg63;
        } else {
            float p, pf, ww; int fi;
            p = fminf(fmaxf(p0, 0.0f), 63.0f); pf = floorf(p); ww = p - pf; fi = (int)pf;
            oA.x = Lg[fi] + ww * (Lg[fi + 1] - Lg[fi]);
            p = fminf(fmaxf(p1, 0.0f), 63.0f); pf = floorf(p); ww = p - pf; fi = (int)pf;
            oA.y = Lg[fi] + ww * (Lg[fi + 1] - Lg[fi]);
            p = fminf(fmaxf(p2, 0.0f), 63.0f); pf = floorf(p); ww = p - pf; fi = (int)pf;
            oA.z = Lg[fi] + ww * (Lg[fi + 1] - Lg[fi]);
            p = fminf(fmaxf(p3, 0.0f), 63.0f); pf = floorf(p); ww = p - pf; fi = (int)pf;
            oA.w = Lg[fi] + ww * (Lg[fi + 1] - Lg[fi]);
        }
    }
    // Chunk B suffix positions.
    {
        const float p0 = total - exclB;
        const float p1 = p0 - g[4];
        const float p2 = p1 - g[5];
        const float p3 = p2 - g[6];
        if (p3 >= 63.0f) {
            oB.x = Lg63; oB.y = Lg63; oB.z = Lg63; oB.w = Lg63;
        } else {
            float p, pf, ww; int fi;
            p = fminf(fmaxf(p0, 0.0f), 63.0f); pf = floorf(p); ww = p - pf; fi = (int)pf;
            oB.x = Lg[fi] + ww * (Lg[fi + 1] - Lg[fi]);
            p = fminf(fmaxf(p1, 0.0f), 63.0f); pf = floorf(p); ww = p - pf; fi = (int)pf;
            oB.y = Lg[fi] + ww * (Lg[fi + 1] - Lg[fi]);
            p = fminf(fmaxf(p2, 0.0f), 63.0f); pf = floorf(p); ww = p - pf; fi = (int)pf;
            oB.z = Lg[fi] + ww * (Lg[fi + 1] - Lg[fi]);
            p = fminf(fmaxf(p3, 0.0f), 63.0f); pf = floorf(p); ww = p - pf; fi = (int)pf;
            oB.w = Lg[fi] + ww * (Lg[fi + 1] - Lg[fi]);
        }
    }

    float4* orow = reinterpret_cast<float4*>(out) + (size_t)row * (L_SEQ / 4);
    __stcs(&orow[t],       oA);
    __stcs(&orow[t + 128], oB);
}

extern "C" void kernel_launch(void* const* d_in, const int* in_sizes, int n_in,
                              void* d_out, int out_size) {
    const float* query = (const float*)d_in[0];   // [4,12,1024,64]
    const float* attn  = (const float*)d_in[1];   // [4,12,1024,1024]
    const float* pe    = (const float*)d_in[2];   // [64,64]
    float* out = (float*)d_out;                   // [4,12,1024,1024]

    const int rows = in_sizes[1] / L_SEQ;         // 49152
    gemv_kernel<<<rows / 32, 256>>>(query, pe);
    cope_main<<<rows, 128>>>(attn, out);
}

// round 7
// speedup vs baseline: 1.5777x; 1.2070x over previous
#include <cuda_runtime.h>
#include <cuda_bf16.h>

#define L_SEQ 1024
#define NPOS  64
#define ROWS_TOTAL (4 * 12 * 1024)

// Scratch: lint[row][n] = q[row,:] . pe[:,n]
__device__ float g_lint[(size_t)ROWS_TOTAL * NPOS];

__device__ __forceinline__ void fma2(unsigned long long& acc,
                                     unsigned long long a,
                                     unsigned long long b) {
    asm("fma.rn.f32x2 %0, %1, %2, %0;" : "+l"(acc) : "l"(a), "l"(b));
}

// ---------------------------------------------------------------------------
// Kernel 1: lint = query @ pos_emb   ([49152,64] @ [64,64])
// Block = 256 threads, 32 rows.  lane -> row, warp -> 8 output cols.
// q staged coalesced into transposed smem (pitch 33, conflict-free reads);
// pe staged in smem, read as warp-broadcast LDS.128; packed f32x2 FMA.
// ---------------------------------------------------------------------------
__global__ __launch_bounds__(256) void gemv_kernel(
    const float* __restrict__ q, const float* __restrict__ pe)
{
    __shared__ float pesh[64 * 64];    // [d][n]
    __shared__ float qshT[64 * 33];    // [d][row], pitch 33

    const int t    = threadIdx.x;
    const int lane = t & 31;
    const int w    = t >> 5;

    // Stage pe (coalesced).
    {
        const float4* src = reinterpret_cast<const float4*>(pe);
        float4*       dst = reinterpret_cast<float4*>(pesh);
        #pragma unroll
        for (int i = 0; i < 4; i++) dst[t + 256 * i] = __ldg(&src[t + 256 * i]);
    }

    // Stage q coalesced, write transposed.
    const int base = blockIdx.x * 32;
    {
        const float4* qsrc = reinterpret_cast<const float4*>(q + (size_t)base * 64);
        #pragma unroll
        for (int h = 0; h < 2; h++) {
            const int i = t + 256 * h;
            const float4 v = __ldg(&qsrc[i]);
            const int row = i >> 4;          // (4i)/64
            const int d0  = (i & 15) << 2;   // (4i)%64
            qshT[(d0 + 0) * 33 + row] = v.x;
            qshT[(d0 + 1) * 33 + row] = v.y;
            qshT[(d0 + 2) * 33 + row] = v.z;
            qshT[(d0 + 3) * 33 + row] = v.w;
        }
    }
    __syncthreads();

    const int cb = w * 8;
    unsigned long long acc0 = 0, acc1 = 0, acc2 = 0, acc3 = 0;
    #pragma unroll
    for (int k = 0; k < 64; k++) {
        const float qk = qshT[k * 33 + lane];
        unsigned long long q2;
        asm("mov.b64 %0, {%1, %1};" : "=l"(q2) : "r"(__float_as_uint(qk)));
        const ulonglong2* pp = reinterpret_cast<const ulonglong2*>(&pesh[k * NPOS + cb]);
        const ulonglong2 pv0 = pp[0];   // cols cb..cb+3 (broadcast LDS.128)
        const ulonglong2 pv1 = pp[1];   // cols cb+4..cb+7
        fma2(acc0, pv0.x, q2);
        fma2(acc1, pv0.y, q2);
        fma2(acc2, pv1.x, q2);
        fma2(acc3, pv1.y, q2);
    }

    const int row = base + lane;
    ulonglong2* o = reinterpret_cast<ulonglong2*>(&g_lint[(size_t)row * NPOS + cb]);
    ulonglong2 r0; r0.x = acc0; r0.y = acc1;
    ulonglong2 r1; r1.x = acc2; r1.y = acc3;
    o[0] = r0;
    o[1] = r1;
}

// ---------------------------------------------------------------------------
// Kernel 2: per row of 1024: gates = sigmoid(attn) (diag zeroed),
// pos = clamp(suffix_sum, 0, 63), out = lerp(Lg[floor], Lg[floor+1], frac).
// 128 threads; thread t owns elements [4t,4t+4) and [512+4t,512+4t+4).
// ---------------------------------------------------------------------------
__global__ __launch_bounds__(128) void cope_main(
    const float* __restrict__ attn,
    float* __restrict__ out)
{
    const int row  = blockIdx.x;
    const int diag = row & (L_SEQ - 1);
    const int t    = threadIdx.x;
    const int lane = t & 31;
    const int w    = t >> 5;

    __shared__ float Lg[NPOS + 1];        // Lg[64] = Lg[63] (weight 0 there)
    __shared__ float wsumA[4], wsumB[4];

    const float4* arow = reinterpret_cast<const float4*>(attn) + (size_t)row * (L_SEQ / 4);
    const float4 va = __ldcs(&arow[t]);
    const float4 vb = __ldcs(&arow[t + 128]);
    if (t < NPOS + 1) {
        const int idx = (t < NPOS) ? t : (NPOS - 1);
        Lg[t] = g_lint[(size_t)row * NPOS + idx];
    }

    float g[8];
    g[0] = __fdividef(1.0f, 1.0f + __expf(-va.x));
    g[1] = __fdividef(1.0f, 1.0f + __expf(-va.y));
    g[2] = __fdividef(1.0f, 1.0f + __expf(-va.z));
    g[3] = __fdividef(1.0f, 1.0f + __expf(-va.w));
    g[4] = __fdividef(1.0f, 1.0f + __expf(-vb.x));
    g[5] = __fdividef(1.0f, 1.0f + __expf(-vb.y));
    g[6] = __fdividef(1.0f, 1.0f + __expf(-vb.z));
    g[7] = __fdividef(1.0f, 1.0f + __expf(-vb.w));

    const int cA = t << 2;
    const int cB = 512 + (t << 2);
    #pragma unroll
    for (int i = 0; i < 4; i++) if (cA + i == diag) g[i] = 0.0f;
    #pragma unroll
    for (int i = 0; i < 4; i++) if (cB + i == diag) g[4 + i] = 0.0f;

    const float sA = g[0] + g[1] + g[2] + g[3];
    const float sB = g[4] + g[5] + g[6] + g[7];

    // Warp inclusive scans over the two chunk sums.
    float iA = sA, iB = sB;
    #pragma unroll
    for (int off = 1; off < 32; off <<= 1) {
        const float nA = __shfl_up_sync(0xffffffffu, iA, off);
        const float nB = __shfl_up_sync(0xffffffffu, iB, off);
        if (lane >= off) { iA += nA; iB += nB; }
    }
    if (lane == 31) { wsumA[w] = iA; wsumB[w] = iB; }
    __syncthreads();

    float totA = 0.0f, totB = 0.0f, preA = 0.0f, preB = 0.0f;
    #pragma unroll
    for (int k = 0; k < 4; k++) {
        const float a = wsumA[k], b = wsumB[k];
        totA += a; totB += b;
        if (k < w) { preA += a; preB += b; }
    }
    const float total = totA + totB;
    const float exclA = preA + iA - sA;
    const float exclB = totA + preB + iB - sB;

    const float Lg63 = Lg[NPOS - 1];
    float4 oA, oB;

    {
        const float p0 = total - exclA;
        const float p1 = p0 - g[0];
        const float p2 = p1 - g[1];
        const float p3 = p2 - g[2];
        if (p3 >= 63.0f) {
            oA.x = Lg63; oA.y = Lg63; oA.z = Lg63; oA.w = Lg63;
        } else {
            float p, pf, ww; int fi;
            p = fminf(fmaxf(p0, 0.0f), 63.0f); pf = floorf(p); ww = p - pf; fi = (int)pf;
            oA.x = Lg[fi] + ww * (Lg[fi + 1] - Lg[fi]);
            p = fminf(fmaxf(p1, 0.0f), 63.0f); pf = floorf(p); ww = p - pf; fi = (int)pf;
            oA.y = Lg[fi] + ww * (Lg[fi + 1] - Lg[fi]);
            p = fminf(fmaxf(p2, 0.0f), 63.0f); pf = floorf(p); ww = p - pf; fi = (int)pf;
            oA.z = Lg[fi] + ww * (Lg[fi + 1] - Lg[fi]);
            p = fminf(fmaxf(p3, 0.0f), 63.0f); pf = floorf(p); ww = p - pf; fi = (int)pf;
            oA.w = Lg[fi] + ww * (Lg[fi + 1] - Lg[fi]);
        }
    }
    {
        const float p0 = total - exclB;
        const float p1 = p0 - g[4];
        const float p2 = p1 - g[5];
        const float p3 = p2 - g[6];
        if (p3 >= 63.0f) {
            oB.x = Lg63; oB.y = Lg63; oB.z = Lg63; oB.w = Lg63;
        } else {
            float p, pf, ww; int fi;
            p = fminf(fmaxf(p0, 0.0f), 63.0f); pf = floorf(p); ww = p - pf; fi = (int)pf;
            oB.x = Lg[fi] + ww * (Lg[fi + 1] - Lg[fi]);
            p = fminf(fmaxf(p1, 0.0f), 63.0f); pf = floorf(p); ww = p - pf; fi = (int)pf;
            oB.y = Lg[fi] + ww * (Lg[fi + 1] - Lg[fi]);
            p = fminf(fmaxf(p2, 0.0f), 63.0f); pf = floorf(p); ww = p - pf; fi = (int)pf;
            oB.z = Lg[fi] + ww * (Lg[fi + 1] - Lg[fi]);
            p = fminf(fmaxf(p3, 0.0f), 63.0f); pf = floorf(p); ww = p - pf; fi = (int)pf;
            oB.w = Lg[fi] + ww * (Lg[fi + 1] - Lg[fi]);
        }
    }

    float4* orow = reinterpret_cast<float4*>(out) + (size_t)row * (L_SEQ / 4);
    __stcs(&orow[t],       oA);
    __stcs(&orow[t + 128], oB);
}

extern "C" void kernel_launch(void* const* d_in, const int* in_sizes, int n_in,
                              void* d_out, int out_size) {
    const float* query = (const float*)d_in[0];   // [4,12,1024,64]
    const float* attn  = (const float*)d_in[1];   // [4,12,1024,1024]
    const float* pe    = (const float*)d_in[2];   // [64,64]
    float* out = (float*)d_out;                   // [4,12,1024,1024]

    const int rows = in_sizes[1] / L_SEQ;         // 49152
    gemv_kernel<<<rows / 32, 256>>>(query, pe);
    cope_main<<<rows, 128>>>(attn, out);
}

// round 8
// speedup vs baseline: 1.8391x; 1.1657x over previous
#include <cuda_runtime.h>
#include <cuda_bf16.h>

#define L_SEQ 1024
#define NPOS  64

// ---------------------------------------------------------------------------
// Fully fused CoPE kernel. One block (128 threads) per row of 1024:
//   Lg[n]  = q_row . pe[:,n]                (in-block 64x64 GEMV, ~32 FMA/thr)
//   gates  = sigmoid(attn_row), diag zeroed
//   pos    = clamp(suffix_sum(gates), 0, 63)
//   out    = lerp(Lg[floor(pos)], Lg[floor(pos)+1], frac(pos))
// Thread t owns attn elements [4t,4t+4) and [512+4t,512+4t+4).
// GEMV: quad = t&15 (output cols 4q..4q+3), dh = t>>4 (d in [8dh,8dh+8)).
// ---------------------------------------------------------------------------
__global__ __launch_bounds__(128) void cope_fused(
    const float* __restrict__ query,      // [rows, 64]
    const float* __restrict__ attn,       // [rows, 1024]
    const float* __restrict__ pe,         // [64, 64] (d, n)
    float* __restrict__ out)              // [rows, 1024]
{
    const int row  = blockIdx.x;
    const int diag = row & (L_SEQ - 1);
    const int t    = threadIdx.x;
    const int lane = t & 31;
    const int w    = t >> 5;

    __shared__ float Lp[8][64];           // GEMV partials [dh][n]
    __shared__ float Lg[NPOS + 1];        // Lg[64] = Lg[63] (weight 0 there)
    __shared__ float wsumA[4], wsumB[4];

    // ---- attn loads first: the DRAM-bound long poles ----
    const float4* arow = reinterpret_cast<const float4*>(attn) + (size_t)row * (L_SEQ / 4);
    const float4 va = __ldcs(&arow[t]);
    const float4 vb = __ldcs(&arow[t + 128]);

    // ---- GEMV partials (q via broadcast LDG, pe L1-resident) ----
    const int quad = t & 15;
    const int dh   = t >> 4;
    {
        const float4* q4 = reinterpret_cast<const float4*>(query) + (size_t)row * 16;
        const float4 qa = __ldg(&q4[dh * 2]);
        const float4 qb = __ldg(&q4[dh * 2 + 1]);
        const float qd[8] = {qa.x, qa.y, qa.z, qa.w, qb.x, qb.y, qb.z, qb.w};
        const float4* pe4 = reinterpret_cast<const float4*>(pe);
        float4 a = make_float4(0.f, 0.f, 0.f, 0.f);
        #pragma unroll
        for (int j = 0; j < 8; j++) {
            const float4 pv = __ldg(&pe4[(dh * 8 + j) * (NPOS / 4) + quad]);
            a.x = fmaf(qd[j], pv.x, a.x);
            a.y = fmaf(qd[j], pv.y, a.y);
            a.z = fmaf(qd[j], pv.z, a.z);
            a.w = fmaf(qd[j], pv.w, a.w);
        }
        *reinterpret_cast<float4*>(&Lp[dh][quad * 4]) = a;
    }

    // ---- sigmoid + diagonal zero ----
    float g[8];
    g[0] = __fdividef(1.0f, 1.0f + __expf(-va.x));
    g[1] = __fdividef(1.0f, 1.0f + __expf(-va.y));
    g[2] = __fdividef(1.0f, 1.0f + __expf(-va.z));
    g[3] = __fdividef(1.0f, 1.0f + __expf(-va.w));
    g[4] = __fdividef(1.0f, 1.0f + __expf(-vb.x));
    g[5] = __fdividef(1.0f, 1.0f + __expf(-vb.y));
    g[6] = __fdividef(1.0f, 1.0f + __expf(-vb.z));
    g[7] = __fdividef(1.0f, 1.0f + __expf(-vb.w));

    const int cA = t << 2;
    const int cB = 512 + (t << 2);
    #pragma unroll
    for (int i = 0; i < 4; i++) if (cA + i == diag) g[i] = 0.0f;
    #pragma unroll
    for (int i = 0; i < 4; i++) if (cB + i == diag) g[4 + i] = 0.0f;

    const float sA = g[0] + g[1] + g[2] + g[3];
    const float sB = g[4] + g[5] + g[6] + g[7];

    // ---- warp inclusive scans over the two chunk sums ----
    float iA = sA, iB = sB;
    #pragma unroll
    for (int off = 1; off < 32; off <<= 1) {
        const float nA = __shfl_up_sync(0xffffffffu, iA, off);
        const float nB = __shfl_up_sync(0xffffffffu, iB, off);
        if (lane >= off) { iA += nA; iB += nB; }
    }
    if (lane == 31) { wsumA[w] = iA; wsumB[w] = iB; }
    __syncthreads();   // Lp + wsum* visible

    // ---- Lg column reduce (threads 0..63) ----
    if (t < NPOS) {
        const float s = ((Lp[0][t] + Lp[1][t]) + (Lp[2][t] + Lp[3][t]))
                      + ((Lp[4][t] + Lp[5][t]) + (Lp[6][t] + Lp[7][t]));
        Lg[t] = s;
        if (t == NPOS - 1) Lg[NPOS] = s;
    }

    // ---- block scan combine (register math, overlaps Lg reduce) ----
    float totA = 0.0f, totB = 0.0f, preA = 0.0f, preB = 0.0f;
    #pragma unroll
    for (int k = 0; k < 4; k++) {
        const float a = wsumA[k], b = wsumB[k];
        totA += a; totB += b;
        if (k < w) { preA += a; preB += b; }
    }
    const float total = totA + totB;
    const float exclA = preA + iA - sA;          // exclusive prefix at cA
    const float exclB = totA + preB + iB - sB;   // exclusive prefix at cB
    __syncthreads();   // Lg visible

    const float Lg63 = Lg[NPOS - 1];
    float4 oA, oB;

    // ---- chunk A: suffix positions + interpolation ----
    {
        const float p0 = total - exclA;
        const float p1 = p0 - g[0];
        const float p2 = p1 - g[1];
        const float p3 = p2 - g[2];
        if (p3 >= 63.0f) {
            oA.x = Lg63; oA.y = Lg63; oA.z = Lg63; oA.w = Lg63;
        } else {
            float p, pf, ww; int fi;
            p = fminf(fmaxf(p0, 0.0f), 63.0f); pf = floorf(p); ww = p - pf; fi = (int)pf;
            oA.x = Lg[fi] + ww * (Lg[fi + 1] - Lg[fi]);
            p = fminf(fmaxf(p1, 0.0f), 63.0f); pf = floorf(p); ww = p - pf; fi = (int)pf;
            oA.y = Lg[fi] + ww * (Lg[fi + 1] - Lg[fi]);
            p = fminf(fmaxf(p2, 0.0f), 63.0f); pf = floorf(p); ww = p - pf; fi = (int)pf;
            oA.z = Lg[fi] + ww * (Lg[fi + 1] - Lg[fi]);
            p = fminf(fmaxf(p3, 0.0f), 63.0f); pf = floorf(p); ww = p - pf; fi = (int)pf;
            oA.w = Lg[fi] + ww * (Lg[fi + 1] - Lg[fi]);
        }
    }
    // ---- chunk B ----
    {
        const float p0 = total - exclB;
        const float p1 = p0 - g[4];
        const float p2 = p1 - g[5];
        const float p3 = p2 - g[6];
        if (p3 >= 63.0f) {
            oB.x = Lg63; oB.y = Lg63; oB.z = Lg63; oB.w = Lg63;
        } else {
            float p, pf, ww; int fi;
            p = fminf(fmaxf(p0, 0.0f), 63.0f); pf = floorf(p); ww = p - pf; fi = (int)pf;
            oB.x = Lg[fi] + ww * (Lg[fi + 1] - Lg[fi]);
            p = fminf(fmaxf(p1, 0.0f), 63.0f); pf = floorf(p); ww = p - pf; fi = (int)pf;
            oB.y = Lg[fi] + ww * (Lg[fi + 1] - Lg[fi]);
            p = fminf(fmaxf(p2, 0.0f), 63.0f); pf = floorf(p); ww = p - pf; fi = (int)pf;
            oB.z = Lg[fi] + ww * (Lg[fi + 1] - Lg[fi]);
            p = fminf(fmaxf(p3, 0.0f), 63.0f); pf = floorf(p); ww = p - pf; fi = (int)pf;
            oB.w = Lg[fi] + ww * (Lg[fi + 1] - Lg[fi]);
        }
    }

    float4* orow = reinterpret_cast<float4*>(out) + (size_t)row * (L_SEQ / 4);
    __stcs(&orow[t],       oA);
    __stcs(&orow[t + 128], oB);
}

extern "C" void kernel_launch(void* const* d_in, const int* in_sizes, int n_in,
                              void* d_out, int out_size) {
    const float* query = (const float*)d_in[0];   // [4,12,1024,64]
    const float* attn  = (const float*)d_in[1];   // [4,12,1024,1024]
    const float* pe    = (const float*)d_in[2];   // [64,64]
    float* out = (float*)d_out;                   // [4,12,1024,1024]

    const int rows = in_sizes[1] / L_SEQ;         // 49152
    cope_fused<<<rows, 128>>>(query, attn, pe, out);
}